// round 16
// baseline (speedup 1.0000x reference)
#include <cuda_runtime.h>
#include <cuda_bf16.h>
#include <math.h>
#include <stdint.h>

#define NROWS 65536
#define DD    512
#define NSPLIT 29
#define KCHTOT 2048
#define PCTAS 128
static __device__ __constant__ float kInvTemp = 0.1f;

typedef unsigned long long u64;
typedef __nv_bfloat16 bf16;

// ---------------------------------------------------------------------------
// helpers
// ---------------------------------------------------------------------------
__device__ __forceinline__ uint32_t smem_u32(const void* p) {
    uint32_t a;
    asm("{ .reg .u64 t; cvta.to.shared.u64 t, %1; cvt.u32.u64 %0, t; }"
        : "=r"(a) : "l"(p));
    return a;
}
__device__ __forceinline__ void cp16(uint32_t dst, const void* src) {
    asm volatile("cp.async.cg.shared.global [%0], [%1], 16;"
                 :: "r"(dst), "l"(src) : "memory");
}
__device__ __forceinline__ void mma16816(float* c, const uint32_t* a,
                                         const uint32_t* b) {
    asm volatile(
        "mma.sync.aligned.m16n8k16.row.col.f32.bf16.bf16.f32 "
        "{%0,%1,%2,%3}, {%4,%5,%6,%7}, {%8,%9}, {%0,%1,%2,%3};"
        : "+f"(c[0]), "+f"(c[1]), "+f"(c[2]), "+f"(c[3])
        : "r"(a[0]), "r"(a[1]), "r"(a[2]), "r"(a[3]), "r"(b[0]), "r"(b[1]));
}
__device__ __forceinline__ void ldsm4(uint32_t* r, uint32_t addr) {
    asm volatile("ldmatrix.sync.aligned.m8n8.x4.shared.b16 {%0,%1,%2,%3}, [%4];"
                 : "=r"(r[0]), "=r"(r[1]), "=r"(r[2]), "=r"(r[3]) : "r"(addr));
}
__device__ __forceinline__ int sw(int r, int k) {
    int s = ((k >> 3) ^ (r & 3) ^ ((r >> 2) & 1)) & 3;
    return r * 64 + s * 16 + (k & 7) * 2;
}
__device__ __forceinline__ void split2(float x, bf16 &hi, bf16 &lo) {
    hi = __float2bfloat16_rn(x);
    lo = __float2bfloat16_rn(x - __bfloat162float(hi));
}
__device__ __forceinline__ uint32_t pack2(bf16 a, bf16 b) {
    __nv_bfloat162 v(a, b);
    return *reinterpret_cast<uint32_t*>(&v);
}
__device__ __forceinline__ void ffma2(u64 &d, u64 a, u64 b) {
    asm("fma.rn.f32x2 %0, %1, %2, %0;" : "+l"(d) : "l"(a), "l"(b));
}
__device__ __forceinline__ float2 upk2(u64 v) {
    float2 r;
    asm("mov.b64 {%0, %1}, %2;" : "=f"(r.x), "=f"(r.y) : "l"(v));
    return r;
}
__device__ __forceinline__ u64 dup2(float x) {
    u64 r;
    asm("mov.b64 %0, {%1, %1};" : "=l"(r) : "f"(x));
    return r;
}

// ---------------------------------------------------------------------------
// scratch
// ---------------------------------------------------------------------------
__device__ float g_colpart[256 * DD];
__device__ float g_mean[DD];
__device__ float g_mcv[3 * DD];
__device__ float g_covpart[(size_t)NSPLIT * DD * DD];
__device__ float g_sig[DD * DD];
__device__ float g_cov[DD * DD];
__device__ float g_T1[DD * DD];
__device__ float g_M[DD * DD];
__device__ float g_MeffA[DD * DD];
__device__ float g_MeffB[DD * DD];
__device__ float g_P0[DD * DD];
__device__ float g_P1[DD * DD];
__device__ float g_A1[DD * DD];
__device__ float g_A2[DD * DD];
__device__ float g_scal[2];
__device__ unsigned g_barCount;
__device__ unsigned g_barGen;
__device__ bf16 g_sA0[(size_t)NROWS * DD];
__device__ bf16 g_sA1[(size_t)NROWS * DD];
__device__ bf16 g_t0[(size_t)DD * NROWS];
__device__ bf16 g_t1[(size_t)DD * NROWS];
__device__ bf16 g_w0[3 * DD * DD];
__device__ bf16 g_w1[3 * DD * DD];

__constant__ int cTI[10] = {0,0,0,0,1,1,1,2,2,3};
__constant__ int cTJ[10] = {0,1,2,3,1,2,3,2,3,3};

// ---------------------------------------------------------------------------
// Big bf16-split mma.sync GEMM (unchanged, round-10 proven)
// ---------------------------------------------------------------------------
#define STAGE_BYTES 32768
#define SMEMSZ (2 * STAGE_BYTES)

template <int MODE>
__global__ __launch_bounds__(256, 2)
void mma_gemm(const bf16* __restrict__ a0g, const bf16* __restrict__ a1g,
              const bf16* __restrict__ b0g, const bf16* __restrict__ b1g,
              float* __restrict__ out, const float* __restrict__ mc) {
    constexpr int LD = (MODE == 2) ? NROWS : DD;

    extern __shared__ __align__(128) char sm[];
    const uint32_t smb = smem_u32(sm);

    const int tid = threadIdx.x;
    const int lane = tid & 31, wid = tid >> 5;
    const int warpRow = wid & 1;
    const int warpCol = wid >> 1;
    const int g = lane >> 2, t4 = lane & 3;
    const int laneRow = lane & 7, grp = lane >> 3;

    int rowBase, colBase, nch;
    size_t kStart;
    float* outp;
    if (MODE == 2) {
        rowBase = cTI[blockIdx.x] * 128;
        colBase = cTJ[blockIdx.x] * 128;
        int c0 = (int)((size_t)blockIdx.z * KCHTOT / NSPLIT);
        int c1 = (int)((size_t)(blockIdx.z + 1) * KCHTOT / NSPLIT);
        kStart = (size_t)c0 * 32;
        nch = c1 - c0;
        outp = out + (size_t)blockIdx.z * DD * DD;
    } else {
        rowBase = blockIdx.y * 128;
        colBase = blockIdx.x * 128;
        kStart = 0;
        nch = DD / 32;
        outp = out;
    }

    float acc[4][4][4];
#pragma unroll
    for (int mi = 0; mi < 4; mi++)
#pragma unroll
        for (int ni = 0; ni < 4; ni++)
#pragma unroll
            for (int q = 0; q < 4; q++) acc[mi][ni][q] = 0.f;

    uint32_t aOff[4], bOff[2];
#pragma unroll
    for (int mi = 0; mi < 4; mi++)
        aOff[mi] = sw(warpRow * 64 + mi * 16 + (grp & 1) * 8 + laneRow, (grp >> 1) * 8);
#pragma unroll
    for (int p = 0; p < 2; p++)
        bOff[p] = sw(warpCol * 32 + p * 16 + (grp >> 1) * 8 + laneRow, (grp & 1) * 8);

    const int lr = tid >> 2;
    const int lseg = tid & 3;

    auto load_chunk = [&](int ch, int stage) {
        const size_t kpos = kStart + (size_t)ch * 32;
        const uint32_t sb = smb + stage * STAGE_BYTES;
#pragma unroll
        for (int i = 0; i < 2; i++) {
            const int r = lr + i * 64;
            const int soff = sw(r, lseg * 8);
            const size_t ga = (size_t)(rowBase + r) * LD + kpos + lseg * 8;
            const size_t gb = (size_t)(colBase + r) * LD + kpos + lseg * 8;
            cp16(sb + soff,         a0g + ga);
            cp16(sb + 8192 + soff,  a1g + ga);
            cp16(sb + 16384 + soff, b0g + gb);
            cp16(sb + 24576 + soff, b1g + gb);
        }
        asm volatile("cp.async.commit_group;" ::: "memory");
    };

    load_chunk(0, 0);

    for (int ch = 0; ch < nch; ch++) {
        if (ch + 1 < nch) {
            load_chunk(ch + 1, (ch + 1) & 1);
            asm volatile("cp.async.wait_group 1;" ::: "memory");
        } else {
            asm volatile("cp.async.wait_group 0;" ::: "memory");
        }
        __syncthreads();

        const uint32_t sA0 = smb + (ch & 1) * STAGE_BYTES;
        const uint32_t sA1 = sA0 + 8192;
        const uint32_t sB0 = sA0 + 16384;
        const uint32_t sB1 = sA0 + 24576;

#pragma unroll
        for (int ks = 0; ks < 2; ks++) {
            const uint32_t kx = ks * 32;
            uint32_t fa0[4][4], fa1[4][4], fb0[2][4], fb1[2][4];
#pragma unroll
            for (int mi = 0; mi < 4; mi++) {
                ldsm4(fa0[mi], sA0 + (aOff[mi] ^ kx));
                ldsm4(fa1[mi], sA1 + (aOff[mi] ^ kx));
            }
#pragma unroll
            for (int p = 0; p < 2; p++) {
                ldsm4(fb0[p], sB0 + (bOff[p] ^ kx));
                ldsm4(fb1[p], sB1 + (bOff[p] ^ kx));
            }
#pragma unroll
            for (int t = 0; t < 3; t++) {
#pragma unroll
                for (int ni = 0; ni < 4; ni++) {
                    const uint32_t* bb =
                        (t == 1) ? &fb1[ni >> 1][(ni & 1) * 2]
                                 : &fb0[ni >> 1][(ni & 1) * 2];
#pragma unroll
                    for (int mi = 0; mi < 4; mi++) {
                        const uint32_t* aa = (t == 2) ? fa1[mi] : fa0[mi];
                        mma16816(acc[mi][ni], aa, bb);
                    }
                }
            }
        }
        __syncthreads();
    }

#pragma unroll
    for (int mi = 0; mi < 4; mi++) {
        const int row0 = rowBase + warpRow * 64 + mi * 16 + g;
#pragma unroll
        for (int ni = 0; ni < 4; ni++) {
            const int col = colBase + warpCol * 32 + ni * 8 + t4 * 2;
            float v0 = acc[mi][ni][0], v1 = acc[mi][ni][1];
            float v2 = acc[mi][ni][2], v3 = acc[mi][ni][3];
            if (MODE == 3) {
                const float m0 = mc[col], m1 = mc[col + 1];
                v0 -= m0; v1 -= m1; v2 -= m0; v3 -= m1;
            }
            *(float2*)(outp + (size_t)row0 * DD + col)       = make_float2(v0, v1);
            *(float2*)(outp + (size_t)(row0 + 8) * DD + col) = make_float2(v2, v3);
        }
    }
}

// ---------------------------------------------------------------------------
// split / transpose / reduction kernels
// ---------------------------------------------------------------------------
__global__ void split_rows2_kernel(const float* __restrict__ in,
                                   bf16* __restrict__ s0, bf16* __restrict__ s1,
                                   int n4) {
    int idx = blockIdx.x * 256 + threadIdx.x;
    if (idx >= n4) return;
    float4 v = ((const float4*)in)[idx];
    bf16 h0, l0, h1, l1, h2, l2, h3, l3;
    split2(v.x, h0, l0); split2(v.y, h1, l1);
    split2(v.z, h2, l2); split2(v.w, h3, l3);
    ((uint2*)s0)[idx] = make_uint2(pack2(h0, h1), pack2(h2, h3));
    ((uint2*)s1)[idx] = make_uint2(pack2(l0, l1), pack2(l2, l3));
}

__global__ void split_trans2_kernel(const float* __restrict__ src,
                                    bf16* __restrict__ t0, bf16* __restrict__ t1,
                                    int ldout) {
    __shared__ float ts[32][33];
    const int tid = threadIdx.x;
    const int n0 = blockIdx.x * 32;
    const int d0 = blockIdx.y * 32;
    int r = tid >> 3, c = (tid & 7) * 4;
    float4 v = *(const float4*)(src + (size_t)(n0 + r) * DD + d0 + c);
    ts[r][c] = v.x; ts[r][c + 1] = v.y; ts[r][c + 2] = v.z; ts[r][c + 3] = v.w;
    __syncthreads();
    int cc = tid >> 3, rr = (tid & 7) * 4;
    bf16 h[4], l[4];
#pragma unroll
    for (int i = 0; i < 4; i++) split2(ts[rr + i][cc], h[i], l[i]);
    size_t off = (size_t)(d0 + cc) * ldout + n0 + rr;
    *(uint2*)(t0 + off) = make_uint2(pack2(h[0], h[1]), pack2(h[2], h[3]));
    *(uint2*)(t1 + off) = make_uint2(pack2(l[0], l[1]), pack2(l[2], l[3]));
}

__global__ void colsum_kernel(const float* __restrict__ H) {
    const int b = blockIdx.x;
    const int t = threadIdx.x;
    const float* p = H + (size_t)b * 256 * DD + t;
    float s = 0.f;
#pragma unroll 8
    for (int r = 0; r < 256; r++) s += p[(size_t)r * DD];
    g_colpart[b * DD + t] = s;
}

// ---------------------------------------------------------------------------
// Persistent per-layer chain — issue-lean pipelined tile GEMM.
// A stored DUPLICATED in smem (no per-kk dup movs); one sync per chunk.
// ---------------------------------------------------------------------------
__device__ __forceinline__ void gridbar() {
    __syncthreads();
    if (threadIdx.x == 0) {
        __threadfence();
        unsigned g = atomicAdd(&g_barGen, 0u);
        if (atomicAdd(&g_barCount, 1u) == PCTAS - 1) {
            g_barCount = 0;
            __threadfence();
            atomicAdd(&g_barGen, 1u);
        } else {
            while (atomicAdd(&g_barGen, 0u) == g) __nanosleep(64);
        }
        __threadfence();
    }
    __syncthreads();
}

// Pipelined 64xTN tile GEMM over K=512, BK=32, double-buffered, 1 sync/chunk.
// EPI: 0 C=acc*sc ; 1 C=acc+I/temp ; 2 C=1.5*Pin-0.5*acc ; 3 C=acc*sc-(kInvTemp*sc)*Pin
template <int TN>
__device__ void tgemm(float* __restrict__ C, const float* __restrict__ A,
                      const float* __restrict__ B, const float* __restrict__ Pin,
                      float sc, int epi, int ta, int r0, int c0,
                      float (*AsD)[132], float (*Bs)[64], uint32_t bsAddr) {
    constexpr int NP = TN / 32;
    const int tid = threadIdx.x;
    const int tx = tid & 15;
    const int ty = tid >> 4;

    u64 acc[4][NP];
#pragma unroll
    for (int r = 0; r < 4; r++)
#pragma unroll
        for (int j = 0; j < NP; j++) acc[r][j] = 0ull;

    float4 areg[2];
    auto loadA = [&](int ch) {
        const int k0 = ch * 32;
        if (ta == 0) {
#pragma unroll
            for (int i = 0; i < 2; i++) {
                int idx = tid * 2 + i;
                int r = idx >> 3, c4 = idx & 7;
                areg[i] = *(const float4*)(A + (size_t)(r0 + r) * DD + k0 + c4 * 4);
            }
        } else {
#pragma unroll
            for (int i = 0; i < 2; i++) {
                int idx = tid * 2 + i;
                int k = idx >> 4, m4 = idx & 15;
                areg[i] = *(const float4*)(A + (size_t)(k0 + k) * DD + r0 + m4 * 4);
            }
        }
    };
    // store A DUPLICATED: AsD[k][2m],AsD[k][2m+1] = A-value
    auto storeA = [&](int buf) {
        if (ta == 0) {
#pragma unroll
            for (int i = 0; i < 2; i++) {
                int idx = tid * 2 + i;
                int r = idx >> 3, k = (idx & 7) * 4;
                *(u64*)&AsD[buf * 32 + k + 0][r * 2] = dup2(areg[i].x);
                *(u64*)&AsD[buf * 32 + k + 1][r * 2] = dup2(areg[i].y);
                *(u64*)&AsD[buf * 32 + k + 2][r * 2] = dup2(areg[i].z);
                *(u64*)&AsD[buf * 32 + k + 3][r * 2] = dup2(areg[i].w);
            }
        } else {
#pragma unroll
            for (int i = 0; i < 2; i++) {
                int idx = tid * 2 + i;
                int k = idx >> 4, m = (idx & 15) * 4;
                *(u64*)&AsD[buf * 32 + k][(m + 0) * 2] = dup2(areg[i].x);
                *(u64*)&AsD[buf * 32 + k][(m + 1) * 2] = dup2(areg[i].y);
                *(u64*)&AsD[buf * 32 + k][(m + 2) * 2] = dup2(areg[i].z);
                *(u64*)&AsD[buf * 32 + k][(m + 3) * 2] = dup2(areg[i].w);
            }
        }
    };
    auto loadB = [&](int ch, int buf) {
        const int k0 = ch * 32;
#pragma unroll
        for (int i = 0; i < NP; i++) {
            int idx = tid + i * 256;
            int k, n4;
            if (TN == 64) { k = idx >> 4; n4 = idx & 15; }
            else          { k = idx >> 3; n4 = idx & 7; }
            cp16(bsAddr + (uint32_t)(((buf * 32 + k) * 64 + n4 * 4) * 4),
                 B + (size_t)(k0 + k) * DD + c0 + n4 * 4);
        }
        asm volatile("cp.async.commit_group;" ::: "memory");
    };

    // prologue: chunk 0 fully staged
    loadA(0);
    loadB(0, 0);
    asm volatile("cp.async.wait_group 0;" ::: "memory");
    storeA(0);
    __syncthreads();

    for (int ch = 0; ch < 16; ch++) {
        const int buf = ch & 1;
        if (ch + 1 < 16) {
            loadA(ch + 1);
            loadB(ch + 1, buf ^ 1);
        }
#pragma unroll 8
        for (int kk = 0; kk < 32; kk++) {
            ulonglong2 p0 = *(const ulonglong2*)&AsD[buf * 32 + kk][ty * 8];
            ulonglong2 p1 = *(const ulonglong2*)&AsD[buf * 32 + kk][ty * 8 + 4];
            u64 b2[NP];
#pragma unroll
            for (int j = 0; j < NP; j++)
                b2[j] = *(const u64*)&Bs[buf * 32 + kk][(j * 16 + tx) * 2];
#pragma unroll
            for (int j = 0; j < NP; j++) {
                ffma2(acc[0][j], p0.x, b2[j]);
                ffma2(acc[1][j], p0.y, b2[j]);
                ffma2(acc[2][j], p1.x, b2[j]);
                ffma2(acc[3][j], p1.y, b2[j]);
            }
        }
        if (ch + 1 < 16) {
            asm volatile("cp.async.wait_group 0;" ::: "memory");
            storeA(buf ^ 1);
            __syncthreads();
        }
    }

#pragma unroll
    for (int r = 0; r < 4; r++) {
#pragma unroll
        for (int j = 0; j < NP; j++) {
            float2 f = upk2(acc[r][j]);
            const int row = r0 + ty * 4 + r;
            const int col = c0 + (j * 16 + tx) * 2;
            if (epi == 0) {
                f.x *= sc; f.y *= sc;
            } else if (epi == 1) {
                if (row == col)     f.x += kInvTemp;
                if (row == col + 1) f.y += kInvTemp;
            } else if (epi == 2) {
                f.x = 1.5f * Pin[(size_t)row * DD + col]     - 0.5f * f.x;
                f.y = 1.5f * Pin[(size_t)row * DD + col + 1] - 0.5f * f.y;
            } else {
                const float cc2 = kInvTemp * sc;
                f.x = f.x * sc - cc2 * Pin[(size_t)row * DD + col];
                f.y = f.y * sc - cc2 * Pin[(size_t)row * DD + col + 1];
            }
            *(float2*)(C + (size_t)row * DD + col) = f;
        }
    }
}

__global__ __launch_bounds__(256)
void persist_chain(const float* __restrict__ W, bf16* __restrict__ w0,
                   bf16* __restrict__ w1, float* __restrict__ mc,
                   const float* __restrict__ MeffPrev,
                   float* __restrict__ MeffOut, int isL0) {
    __shared__ __align__(16) float AsD[64][132];   // 2 bufs x 32 k, duplicated
    __shared__ __align__(16) float Bs[64][64];
    __shared__ float red[256];
    float (*tsub)[33] = (float(*)[33])&AsD[0][0];
    const uint32_t bsAddr = smem_u32(Bs);

    const int tile = blockIdx.x;
    const int tid = threadIdx.x;
    const int lane = tid & 31;

    const int t64 = (tile < 64) ? tile : tile - 64;
    const int r64 = (t64 >> 3) * 64, c64 = (t64 & 7) * 64;
    const int r32 = (tile >> 4) * 64, c32 = (tile & 15) * 32;

    if (isL0) {
        if (tile < 64) {
            const int col = tile * 8 + (tid >> 5);
            float s = 0.f;
            for (int b = lane; b < 256; b += 32) s += g_colpart[b * DD + col];
#pragma unroll
            for (int o = 16; o > 0; o >>= 1)
                s += __shfl_down_sync(0xffffffffu, s, o);
            if (lane == 0) g_mean[col] = s * (1.0f / (float)NROWS);
        }
        gridbar();
#pragma unroll
        for (int q = 0; q < 8; q++) {
            int idx = tile * 2048 + q * 256 + tid;
            int i = idx >> 9, j = idx & (DD - 1);
            int src = ((i >> 7) <= (j >> 7)) ? (i * DD + j) : (j * DD + i);
            float s = 0.f;
#pragma unroll
            for (int z = 0; z < NSPLIT; z++)
                s += g_covpart[(size_t)z * DD * DD + src];
            g_sig[idx] = s * (1.0f / (float)NROWS) - g_mean[i] * g_mean[j];
        }
        gridbar();
    }

    tgemm<32>(g_T1, g_sig, W, nullptr, 1.0f, 0, 0, r32, c32, AsD, Bs, bsAddr);
    gridbar();
    tgemm<32>(g_cov, W, g_T1, nullptr, 1.0f, 1, 1, r32, c32, AsD, Bs, bsAddr);
    gridbar();
    if (tile == 0) {
        float s = g_cov[(size_t)(2 * tid) * (DD + 1)]
                + g_cov[(size_t)(2 * tid + 1) * (DD + 1)];
        red[tid] = s;
        __syncthreads();
        for (int k = 128; k > 0; k >>= 1) {
            if (tid < k) red[tid] += red[tid + k];
            __syncthreads();
        }
        if (tid == 0) {
            float tr = red[0];
            g_scal[0] = 1.0f / tr;
            g_scal[1] = 1.0f / sqrtf(tr);
        }
    }
    gridbar();
    {
        const float s0 = g_scal[0];
#pragma unroll
        for (int q = 0; q < 8; q++) {
            int idx = tile * 2048 + q * 256 + tid;
            int i = idx >> 9, j = idx & (DD - 1);
            g_P0[idx] = ((i == j) ? 1.5f : 0.0f) - 0.5f * g_cov[idx] * s0;
        }
    }
    gridbar();

    float* P = g_P0;
    float* Pn = g_P1;
    for (int it = 1; it < 10; it++) {
        if (tile < 64)
            tgemm<64>(g_A1, P, P, nullptr, 1.0f, 0, 0, r64, c64, AsD, Bs, bsAddr);
        else
            tgemm<64>(g_A2, P, g_cov, nullptr, g_scal[0], 0, 0, r64, c64, AsD, Bs, bsAddr);
        gridbar();
        tgemm<32>(Pn, g_A1, g_A2, P, 1.0f, 2, 0, r32, c32, AsD, Bs, bsAddr);
        gridbar();
        float* t = P; P = Pn; Pn = t;
    }

    if (tile < 64)
        tgemm<64>(g_A2, P, g_cov, P, g_scal[0], 3, 0, r64, c64, AsD, Bs, bsAddr);
    else
        tgemm<64>(g_M, W, P, nullptr, g_scal[1], 0, 0, r64, c64, AsD, Bs, bsAddr);
    gridbar();
    if (tile < 64) {
        tgemm<64>(g_sig, P, g_A2, nullptr, 1.0f, 0, 0, r64, c64, AsD, Bs, bsAddr);
    } else if (isL0) {
#pragma unroll
        for (int q = 0; q < 16; q++) {
            int idx = (tile - 64) * 4096 + q * 256 + tid;
            MeffOut[idx] = g_M[idx];
        }
    } else {
        tgemm<64>(MeffOut, MeffPrev, g_M, nullptr, 1.0f, 0, 0, r64, c64, AsD, Bs, bsAddr);
    }
    gridbar();
    if (tile < 64) {
        const int br = t64 >> 3, bc = t64 & 7;
#pragma unroll
        for (int sj = 0; sj < 2; sj++)
#pragma unroll
            for (int si = 0; si < 2; si++) {
                int r = tid >> 3, c = (tid & 7) * 4;
                float4 v = *(const float4*)(MeffOut + (size_t)(br * 64 + si * 32 + r) * DD
                                            + bc * 64 + sj * 32 + c);
                tsub[r][c] = v.x; tsub[r][c + 1] = v.y;
                tsub[r][c + 2] = v.z; tsub[r][c + 3] = v.w;
                __syncthreads();
                int cc = tid >> 3, rr = (tid & 7) * 4;
                bf16 h[4], l[4];
#pragma unroll
                for (int i = 0; i < 4; i++) split2(tsub[rr + i][cc], h[i], l[i]);
                size_t off = (size_t)(bc * 64 + sj * 32 + cc) * DD + br * 64 + si * 32 + rr;
                *(uint2*)(w0 + off) = make_uint2(pack2(h[0], h[1]), pack2(h[2], h[3]));
                *(uint2*)(w1 + off) = make_uint2(pack2(l[0], l[1]), pack2(l[2], l[3]));
                __syncthreads();
            }
    } else {
        const int col = (tile - 64) * 8 + (tid >> 5);
        float s = 0.f;
        for (int k = lane; k < DD; k += 32)
            s += g_mean[k] * MeffOut[(size_t)k * DD + col];
#pragma unroll
        for (int o = 16; o > 0; o >>= 1)
            s += __shfl_down_sync(0xffffffffu, s, o);
        if (lane == 0) mc[col] = s;
    }
}

// ---------------------------------------------------------------------------
// orchestration (round-14/15 structure; chain L0 = our 4th launch for ncu)
// ---------------------------------------------------------------------------
static cudaStream_t s2, sO1, sO2;
static cudaEvent_t evRoot, evGram, evSplit, evM[3], evO1, evO2;
static bool g_inited = false;

extern "C" void kernel_launch(void* const* d_in, const int* in_sizes, int n_in,
                              void* d_out, int out_size) {
    (void)in_sizes; (void)n_in; (void)out_size;
    const float* x = (const float*)d_in[0];
    const float* W[3] = {(const float*)d_in[1], (const float*)d_in[2],
                         (const float*)d_in[3]};
    float* out = (float*)d_out;

    float *pcovpart, *pmc, *pMA, *pMB;
    bf16 *psA0, *psA1, *pt0, *pt1, *pw0, *pw1;
    cudaGetSymbolAddress((void**)&pcovpart, g_covpart);
    cudaGetSymbolAddress((void**)&pmc, g_mcv);
    cudaGetSymbolAddress((void**)&pMA, g_MeffA);
    cudaGetSymbolAddress((void**)&pMB, g_MeffB);
    cudaGetSymbolAddress((void**)&psA0, g_sA0);
    cudaGetSymbolAddress((void**)&psA1, g_sA1);
    cudaGetSymbolAddress((void**)&pt0, g_t0);
    cudaGetSymbolAddress((void**)&pt1, g_t1);
    cudaGetSymbolAddress((void**)&pw0, g_w0);
    cudaGetSymbolAddress((void**)&pw1, g_w1);

    if (!g_inited) {
        g_inited = true;
        cudaFuncSetAttribute(mma_gemm<2>, cudaFuncAttributeMaxDynamicSharedMemorySize, SMEMSZ);
        cudaFuncSetAttribute(mma_gemm<3>, cudaFuncAttributeMaxDynamicSharedMemorySize, SMEMSZ);
        cudaStreamCreateWithFlags(&s2, cudaStreamNonBlocking);
        cudaStreamCreateWithFlags(&sO1, cudaStreamNonBlocking);
        cudaStreamCreateWithFlags(&sO2, cudaStreamNonBlocking);
        cudaEventCreateWithFlags(&evRoot, cudaEventDisableTiming);
        cudaEventCreateWithFlags(&evGram, cudaEventDisableTiming);
        cudaEventCreateWithFlags(&evSplit, cudaEventDisableTiming);
        for (int i = 0; i < 3; i++)
            cudaEventCreateWithFlags(&evM[i], cudaEventDisableTiming);
        cudaEventCreateWithFlags(&evO1, cudaEventDisableTiming);
        cudaEventCreateWithFlags(&evO2, cudaEventDisableTiming);
    }

    const int N4BIG = NROWS * DD / 4;
    const dim3 gact(4, NROWS / 128);
    const dim3 gcov(10, 1, NSPLIT);

    split_trans2_kernel<<<dim3(NROWS / 32, 16), 256>>>(x, pt0, pt1, NROWS);     // #1
    cudaEventRecord(evRoot, 0);
    cudaStreamWaitEvent(s2, evRoot, 0);

    colsum_kernel<<<256, 512, 0, s2>>>(x);                                      // #2
    mma_gemm<2><<<gcov, 256, SMEMSZ>>>(pt0, pt1, pt0, pt1, pcovpart, nullptr);  // #3
    cudaEventRecord(evGram, 0);

    cudaStreamWaitEvent(s2, evGram, 0);
    persist_chain<<<PCTAS, 256, 0, s2>>>(W[0], pw0, pw1, pmc,
                                         nullptr, pMA, 1);                      // #4 (ncu)
    cudaEventRecord(evM[0], s2);

    split_rows2_kernel<<<N4BIG / 256, 256>>>(x, psA0, psA1, N4BIG);             // #5
    cudaEventRecord(evSplit, 0);

    persist_chain<<<PCTAS, 256, 0, s2>>>(W[1], pw0 + (size_t)DD * DD,
                                         pw1 + (size_t)DD * DD, pmc + DD,
                                         pMA, pMB, 0);                          // #6
    cudaEventRecord(evM[1], s2);
    persist_chain<<<PCTAS, 256, 0, s2>>>(W[2], pw0 + (size_t)2 * DD * DD,
                                         pw1 + (size_t)2 * DD * DD, pmc + 2 * DD,
                                         pMB, pMA, 0);                          // #7
    cudaEventRecord(evM[2], s2);

    cudaStreamWaitEvent(0, evM[0], 0);
    mma_gemm<3><<<gact, 256, SMEMSZ>>>(psA0, psA1, pw0, pw1, out, pmc);         // #8

    cudaStreamWaitEvent(sO1, evSplit, 0);
    cudaStreamWaitEvent(sO1, evM[1], 0);
    mma_gemm<3><<<gact, 256, SMEMSZ, sO1>>>(psA0, psA1,
                                            pw0 + (size_t)DD * DD,
                                            pw1 + (size_t)DD * DD,
                                            out + (size_t)NROWS * DD, pmc + DD); // #9
    cudaEventRecord(evO1, sO1);

    cudaStreamWaitEvent(sO2, evSplit, 0);
    cudaStreamWaitEvent(sO2, evM[2], 0);
    mma_gemm<3><<<gact, 256, SMEMSZ, sO2>>>(psA0, psA1,
                                            pw0 + (size_t)2 * DD * DD,
                                            pw1 + (size_t)2 * DD * DD,
                                            out + (size_t)2 * NROWS * DD,
                                            pmc + 2 * DD);                       // #10
    cudaEventRecord(evO2, sO2);

    cudaStreamWaitEvent(0, evO1, 0);
    cudaStreamWaitEvent(0, evO2, 0);
}

// round 17
// speedup vs baseline: 1.0026x; 1.0026x over previous
#include <cuda_runtime.h>
#include <cuda_bf16.h>
#include <math.h>
#include <stdint.h>

#define NROWS 65536
#define DD    512
#define NSPLIT 29
#define KCHTOT 2048
#define PCTAS 256
static __device__ __constant__ float kInvTemp = 0.1f;

typedef unsigned long long u64;
typedef __nv_bfloat16 bf16;

// ---------------------------------------------------------------------------
// helpers
// ---------------------------------------------------------------------------
__device__ __forceinline__ uint32_t smem_u32(const void* p) {
    uint32_t a;
    asm("{ .reg .u64 t; cvta.to.shared.u64 t, %1; cvt.u32.u64 %0, t; }"
        : "=r"(a) : "l"(p));
    return a;
}
__device__ __forceinline__ void cp16(uint32_t dst, const void* src) {
    asm volatile("cp.async.cg.shared.global [%0], [%1], 16;"
                 :: "r"(dst), "l"(src) : "memory");
}
__device__ __forceinline__ void mma16816(float* c, const uint32_t* a,
                                         const uint32_t* b) {
    asm volatile(
        "mma.sync.aligned.m16n8k16.row.col.f32.bf16.bf16.f32 "
        "{%0,%1,%2,%3}, {%4,%5,%6,%7}, {%8,%9}, {%0,%1,%2,%3};"
        : "+f"(c[0]), "+f"(c[1]), "+f"(c[2]), "+f"(c[3])
        : "r"(a[0]), "r"(a[1]), "r"(a[2]), "r"(a[3]), "r"(b[0]), "r"(b[1]));
}
__device__ __forceinline__ void ldsm4(uint32_t* r, uint32_t addr) {
    asm volatile("ldmatrix.sync.aligned.m8n8.x4.shared.b16 {%0,%1,%2,%3}, [%4];"
                 : "=r"(r[0]), "=r"(r[1]), "=r"(r[2]), "=r"(r[3]) : "r"(addr));
}
__device__ __forceinline__ int sw(int r, int k) {
    int s = ((k >> 3) ^ (r & 3) ^ ((r >> 2) & 1)) & 3;
    return r * 64 + s * 16 + (k & 7) * 2;
}
__device__ __forceinline__ void split2(float x, bf16 &hi, bf16 &lo) {
    hi = __float2bfloat16_rn(x);
    lo = __float2bfloat16_rn(x - __bfloat162float(hi));
}
__device__ __forceinline__ uint32_t pack2(bf16 a, bf16 b) {
    __nv_bfloat162 v(a, b);
    return *reinterpret_cast<uint32_t*>(&v);
}
__device__ __forceinline__ void ffma2(u64 &d, u64 a, u64 b) {
    asm("fma.rn.f32x2 %0, %1, %2, %0;" : "+l"(d) : "l"(a), "l"(b));
}
__device__ __forceinline__ float2 upk2(u64 v) {
    float2 r;
    asm("mov.b64 {%0, %1}, %2;" : "=f"(r.x), "=f"(r.y) : "l"(v));
    return r;
}
__device__ __forceinline__ u64 dup2(float x) {
    u64 r;
    asm("mov.b64 %0, {%1, %1};" : "=l"(r) : "f"(x));
    return r;
}

// ---------------------------------------------------------------------------
// scratch
// ---------------------------------------------------------------------------
__device__ float g_colpart[256 * DD];
__device__ float g_mean[DD];
__device__ float g_mcv[3 * DD];
__device__ float g_covpart[(size_t)NSPLIT * DD * DD];
__device__ float g_sig[DD * DD];
__device__ float g_cov[DD * DD];
__device__ float g_T1[DD * DD];
__device__ float g_M[DD * DD];
__device__ float g_MeffA[DD * DD];
__device__ float g_MeffB[DD * DD];
__device__ float g_P0[DD * DD];
__device__ float g_P1[DD * DD];
__device__ float g_A1[DD * DD];
__device__ float g_A2[DD * DD];
__device__ float g_scal[2];
__device__ unsigned g_barCount;
__device__ unsigned g_barGen;
__device__ bf16 g_sA0[(size_t)NROWS * DD];
__device__ bf16 g_sA1[(size_t)NROWS * DD];
__device__ bf16 g_t0[(size_t)DD * NROWS];
__device__ bf16 g_t1[(size_t)DD * NROWS];
__device__ bf16 g_w0[3 * DD * DD];
__device__ bf16 g_w1[3 * DD * DD];

__constant__ int cTI[10] = {0,0,0,0,1,1,1,2,2,3};
__constant__ int cTJ[10] = {0,1,2,3,1,2,3,2,3,3};

// ---------------------------------------------------------------------------
// Big bf16-split mma.sync GEMM (unchanged, round-10 proven)
// ---------------------------------------------------------------------------
#define STAGE_BYTES 32768
#define SMEMSZ (2 * STAGE_BYTES)

template <int MODE>
__global__ __launch_bounds__(256, 2)
void mma_gemm(const bf16* __restrict__ a0g, const bf16* __restrict__ a1g,
              const bf16* __restrict__ b0g, const bf16* __restrict__ b1g,
              float* __restrict__ out, const float* __restrict__ mc) {
    constexpr int LD = (MODE == 2) ? NROWS : DD;

    extern __shared__ __align__(128) char sm[];
    const uint32_t smb = smem_u32(sm);

    const int tid = threadIdx.x;
    const int lane = tid & 31, wid = tid >> 5;
    const int warpRow = wid & 1;
    const int warpCol = wid >> 1;
    const int g = lane >> 2, t4 = lane & 3;
    const int laneRow = lane & 7, grp = lane >> 3;

    int rowBase, colBase, nch;
    size_t kStart;
    float* outp;
    if (MODE == 2) {
        rowBase = cTI[blockIdx.x] * 128;
        colBase = cTJ[blockIdx.x] * 128;
        int c0 = (int)((size_t)blockIdx.z * KCHTOT / NSPLIT);
        int c1 = (int)((size_t)(blockIdx.z + 1) * KCHTOT / NSPLIT);
        kStart = (size_t)c0 * 32;
        nch = c1 - c0;
        outp = out + (size_t)blockIdx.z * DD * DD;
    } else {
        rowBase = blockIdx.y * 128;
        colBase = blockIdx.x * 128;
        kStart = 0;
        nch = DD / 32;
        outp = out;
    }

    float acc[4][4][4];
#pragma unroll
    for (int mi = 0; mi < 4; mi++)
#pragma unroll
        for (int ni = 0; ni < 4; ni++)
#pragma unroll
            for (int q = 0; q < 4; q++) acc[mi][ni][q] = 0.f;

    uint32_t aOff[4], bOff[2];
#pragma unroll
    for (int mi = 0; mi < 4; mi++)
        aOff[mi] = sw(warpRow * 64 + mi * 16 + (grp & 1) * 8 + laneRow, (grp >> 1) * 8);
#pragma unroll
    for (int p = 0; p < 2; p++)
        bOff[p] = sw(warpCol * 32 + p * 16 + (grp >> 1) * 8 + laneRow, (grp & 1) * 8);

    const int lr = tid >> 2;
    const int lseg = tid & 3;

    auto load_chunk = [&](int ch, int stage) {
        const size_t kpos = kStart + (size_t)ch * 32;
        const uint32_t sb = smb + stage * STAGE_BYTES;
#pragma unroll
        for (int i = 0; i < 2; i++) {
            const int r = lr + i * 64;
            const int soff = sw(r, lseg * 8);
            const size_t ga = (size_t)(rowBase + r) * LD + kpos + lseg * 8;
            const size_t gb = (size_t)(colBase + r) * LD + kpos + lseg * 8;
            cp16(sb + soff,         a0g + ga);
            cp16(sb + 8192 + soff,  a1g + ga);
            cp16(sb + 16384 + soff, b0g + gb);
            cp16(sb + 24576 + soff, b1g + gb);
        }
        asm volatile("cp.async.commit_group;" ::: "memory");
    };

    load_chunk(0, 0);

    for (int ch = 0; ch < nch; ch++) {
        if (ch + 1 < nch) {
            load_chunk(ch + 1, (ch + 1) & 1);
            asm volatile("cp.async.wait_group 1;" ::: "memory");
        } else {
            asm volatile("cp.async.wait_group 0;" ::: "memory");
        }
        __syncthreads();

        const uint32_t sA0 = smb + (ch & 1) * STAGE_BYTES;
        const uint32_t sA1 = sA0 + 8192;
        const uint32_t sB0 = sA0 + 16384;
        const uint32_t sB1 = sA0 + 24576;

#pragma unroll
        for (int ks = 0; ks < 2; ks++) {
            const uint32_t kx = ks * 32;
            uint32_t fa0[4][4], fa1[4][4], fb0[2][4], fb1[2][4];
#pragma unroll
            for (int mi = 0; mi < 4; mi++) {
                ldsm4(fa0[mi], sA0 + (aOff[mi] ^ kx));
                ldsm4(fa1[mi], sA1 + (aOff[mi] ^ kx));
            }
#pragma unroll
            for (int p = 0; p < 2; p++) {
                ldsm4(fb0[p], sB0 + (bOff[p] ^ kx));
                ldsm4(fb1[p], sB1 + (bOff[p] ^ kx));
            }
#pragma unroll
            for (int t = 0; t < 3; t++) {
#pragma unroll
                for (int ni = 0; ni < 4; ni++) {
                    const uint32_t* bb =
                        (t == 1) ? &fb1[ni >> 1][(ni & 1) * 2]
                                 : &fb0[ni >> 1][(ni & 1) * 2];
#pragma unroll
                    for (int mi = 0; mi < 4; mi++) {
                        const uint32_t* aa = (t == 2) ? fa1[mi] : fa0[mi];
                        mma16816(acc[mi][ni], aa, bb);
                    }
                }
            }
        }
        __syncthreads();
    }

#pragma unroll
    for (int mi = 0; mi < 4; mi++) {
        const int row0 = rowBase + warpRow * 64 + mi * 16 + g;
#pragma unroll
        for (int ni = 0; ni < 4; ni++) {
            const int col = colBase + warpCol * 32 + ni * 8 + t4 * 2;
            float v0 = acc[mi][ni][0], v1 = acc[mi][ni][1];
            float v2 = acc[mi][ni][2], v3 = acc[mi][ni][3];
            if (MODE == 3) {
                const float m0 = mc[col], m1 = mc[col + 1];
                v0 -= m0; v1 -= m1; v2 -= m0; v3 -= m1;
            }
            *(float2*)(outp + (size_t)row0 * DD + col)       = make_float2(v0, v1);
            *(float2*)(outp + (size_t)(row0 + 8) * DD + col) = make_float2(v2, v3);
        }
    }
}

// ---------------------------------------------------------------------------
// split / transpose / reduction kernels
// ---------------------------------------------------------------------------
__global__ void split_rows2_kernel(const float* __restrict__ in,
                                   bf16* __restrict__ s0, bf16* __restrict__ s1,
                                   int n4) {
    int idx = blockIdx.x * 256 + threadIdx.x;
    if (idx >= n4) return;
    float4 v = ((const float4*)in)[idx];
    bf16 h0, l0, h1, l1, h2, l2, h3, l3;
    split2(v.x, h0, l0); split2(v.y, h1, l1);
    split2(v.z, h2, l2); split2(v.w, h3, l3);
    ((uint2*)s0)[idx] = make_uint2(pack2(h0, h1), pack2(h2, h3));
    ((uint2*)s1)[idx] = make_uint2(pack2(l0, l1), pack2(l2, l3));
}

__global__ void split_trans2_kernel(const float* __restrict__ src,
                                    bf16* __restrict__ t0, bf16* __restrict__ t1,
                                    int ldout) {
    __shared__ float ts[32][33];
    const int tid = threadIdx.x;
    const int n0 = blockIdx.x * 32;
    const int d0 = blockIdx.y * 32;
    int r = tid >> 3, c = (tid & 7) * 4;
    float4 v = *(const float4*)(src + (size_t)(n0 + r) * DD + d0 + c);
    ts[r][c] = v.x; ts[r][c + 1] = v.y; ts[r][c + 2] = v.z; ts[r][c + 3] = v.w;
    __syncthreads();
    int cc = tid >> 3, rr = (tid & 7) * 4;
    bf16 h[4], l[4];
#pragma unroll
    for (int i = 0; i < 4; i++) split2(ts[rr + i][cc], h[i], l[i]);
    size_t off = (size_t)(d0 + cc) * ldout + n0 + rr;
    *(uint2*)(t0 + off) = make_uint2(pack2(h[0], h[1]), pack2(h[2], h[3]));
    *(uint2*)(t1 + off) = make_uint2(pack2(l[0], l[1]), pack2(l[2], l[3]));
}

__global__ void colsum_kernel(const float* __restrict__ H) {
    const int b = blockIdx.x;
    const int t = threadIdx.x;
    const float* p = H + (size_t)b * 256 * DD + t;
    float s = 0.f;
#pragma unroll 8
    for (int r = 0; r < 256; r++) s += p[(size_t)r * DD];
    g_colpart[b * DD + t] = s;
}

// ---------------------------------------------------------------------------
// Persistent per-layer chain — R15 pipelined tile GEMM (register-dup A),
// generalized to <RM,NP>; PCTAS=256 for 2 CTAs/SM occupancy.
// ---------------------------------------------------------------------------
__device__ __forceinline__ void gridbar() {
    __syncthreads();
    if (threadIdx.x == 0) {
        __threadfence();
        unsigned g = atomicAdd(&g_barGen, 0u);
        if (atomicAdd(&g_barCount, 1u) == PCTAS - 1) {
            g_barCount = 0;
            __threadfence();
            atomicAdd(&g_barGen, 1u);
        } else {
            while (atomicAdd(&g_barGen, 0u) == g) __nanosleep(64);
        }
        __threadfence();
    }
    __syncthreads();
}

// Pipelined (RM*16)x(NP*32) tile GEMM over K=512, BK=32, double-buffered.
// EPI: 0 C=acc*sc ; 1 C=acc+I/temp ; 2 C=1.5*Pin-0.5*acc ; 3 C=acc*sc-(kInvTemp*sc)*Pin
template <int RM, int NP>
__device__ void tgemm(float* __restrict__ C, const float* __restrict__ A,
                      const float* __restrict__ B, const float* __restrict__ Pin,
                      float sc, int epi, int ta, int r0, int c0,
                      float (*As)[68], float (*Bs)[64], uint32_t bsAddr) {
    const int tid = threadIdx.x;
    const int tx = tid & 15;
    const int ty = tid >> 4;

    u64 acc[RM][NP];
#pragma unroll
    for (int r = 0; r < RM; r++)
#pragma unroll
        for (int j = 0; j < NP; j++) acc[r][j] = 0ull;

    float4 areg[RM / 2];
    auto loadA = [&](int ch) {
        const int k0 = ch * 32;
        if (ta == 0) {
#pragma unroll
            for (int i = 0; i < RM / 2; i++) {
                int idx = tid * (RM / 2) + i;
                int r = idx >> 3, c4 = idx & 7;
                areg[i] = *(const float4*)(A + (size_t)(r0 + r) * DD + k0 + c4 * 4);
            }
        } else {
#pragma unroll
            for (int i = 0; i < RM / 2; i++) {
                int idx = tid * (RM / 2) + i;
                int k = idx / (RM * 4), m4 = idx % (RM * 4);
                areg[i] = *(const float4*)(A + (size_t)(k0 + k) * DD + r0 + m4 * 4);
            }
        }
    };
    auto storeA = [&](int buf) {
        if (ta == 0) {
#pragma unroll
            for (int i = 0; i < RM / 2; i++) {
                int idx = tid * (RM / 2) + i;
                int r = idx >> 3, k = (idx & 7) * 4;
                As[buf * 32 + k + 0][r] = areg[i].x;
                As[buf * 32 + k + 1][r] = areg[i].y;
                As[buf * 32 + k + 2][r] = areg[i].z;
                As[buf * 32 + k + 3][r] = areg[i].w;
            }
        } else {
#pragma unroll
            for (int i = 0; i < RM / 2; i++) {
                int idx = tid * (RM / 2) + i;
                int k = idx / (RM * 4), m4 = idx % (RM * 4);
                *(float4*)&As[buf * 32 + k][m4 * 4] = areg[i];
            }
        }
    };
    auto loadB = [&](int ch, int buf) {
        const int k0 = ch * 32;
#pragma unroll
        for (int i = 0; i < NP; i++) {
            int idx = tid + i * 256;
            int k, n4;
            if (NP == 2) { k = idx >> 4; n4 = idx & 15; }
            else         { k = idx >> 3; n4 = idx & 7; }
            cp16(bsAddr + (uint32_t)(((buf * 32 + k) * 64 + n4 * 4) * 4),
                 B + (size_t)(k0 + k) * DD + c0 + n4 * 4);
        }
        asm volatile("cp.async.commit_group;" ::: "memory");
    };

    loadA(0);
    loadB(0, 0);

    for (int ch = 0; ch < 16; ch++) {
        const int buf = ch & 1;
        if (ch + 1 < 16) loadB(ch + 1, buf ^ 1);
        storeA(buf);
        if (ch + 1 < 16) loadA(ch + 1);
        if (ch + 1 < 16) asm volatile("cp.async.wait_group 1;" ::: "memory");
        else             asm volatile("cp.async.wait_group 0;" ::: "memory");
        __syncthreads();
#pragma unroll 8
        for (int kk = 0; kk < 32; kk++) {
            u64 a2[RM];
            if (RM == 4) {
                float4 a0 = *(const float4*)&As[buf * 32 + kk][ty * 4];
                a2[0] = dup2(a0.x); a2[1] = dup2(a0.y);
                a2[2] = dup2(a0.z); a2[3] = dup2(a0.w);
            } else {
                float2 a0 = *(const float2*)&As[buf * 32 + kk][ty * 2];
                a2[0] = dup2(a0.x); a2[1] = dup2(a0.y);
            }
            u64 b2[NP];
#pragma unroll
            for (int j = 0; j < NP; j++)
                b2[j] = *(const u64*)&Bs[buf * 32 + kk][(j * 16 + tx) * 2];
#pragma unroll
            for (int r = 0; r < RM; r++)
#pragma unroll
                for (int j = 0; j < NP; j++) ffma2(acc[r][j], a2[r], b2[j]);
        }
        __syncthreads();
    }

#pragma unroll
    for (int r = 0; r < RM; r++) {
#pragma unroll
        for (int j = 0; j < NP; j++) {
            float2 f = upk2(acc[r][j]);
            const int row = r0 + ty * RM + r;
            const int col = c0 + (j * 16 + tx) * 2;
            if (epi == 0) {
                f.x *= sc; f.y *= sc;
            } else if (epi == 1) {
                if (row == col)     f.x += kInvTemp;
                if (row == col + 1) f.y += kInvTemp;
            } else if (epi == 2) {
                f.x = 1.5f * Pin[(size_t)row * DD + col]     - 0.5f * f.x;
                f.y = 1.5f * Pin[(size_t)row * DD + col + 1] - 0.5f * f.y;
            } else {
                const float cc2 = kInvTemp * sc;
                f.x = f.x * sc - cc2 * Pin[(size_t)row * DD + col];
                f.y = f.y * sc - cc2 * Pin[(size_t)row * DD + col + 1];
            }
            *(float2*)(C + (size_t)row * DD + col) = f;
        }
    }
}

__global__ __launch_bounds__(256, 2)
void persist_chain(const float* __restrict__ W, bf16* __restrict__ w0,
                   bf16* __restrict__ w1, float* __restrict__ mc,
                   const float* __restrict__ MeffPrev,
                   float* __restrict__ MeffOut, int isL0) {
    __shared__ __align__(16) float As[64][68];
    __shared__ __align__(16) float Bs[64][64];
    __shared__ float red[256];
    float (*tsub)[33] = (float(*)[33])&As[0][0];
    const uint32_t bsAddr = smem_u32(Bs);

    const int tile = blockIdx.x;            // 0..255
    const int tid = threadIdx.x;
    const int lane = tid & 31;

    // dual-stage coords: 128 tiles of 64x32 per GEMM
    const int td = tile & 127;
    const int rD = (td >> 4) * 64, cD = (td & 15) * 32;
    // single-stage coords: 256 tiles of 32x32
    const int rS = (tile >> 4) * 32, cS = (tile & 15) * 32;

    if (isL0) {
        if (tile < 64) {
            const int col = tile * 8 + (tid >> 5);
            float s = 0.f;
            for (int b = lane; b < 256; b += 32) s += g_colpart[b * DD + col];
#pragma unroll
            for (int o = 16; o > 0; o >>= 1)
                s += __shfl_down_sync(0xffffffffu, s, o);
            if (lane == 0) g_mean[col] = s * (1.0f / (float)NROWS);
        }
        gridbar();
#pragma unroll
        for (int q = 0; q < 4; q++) {
            int idx = tile * 1024 + q * 256 + tid;
            int i = idx >> 9, j = idx & (DD - 1);
            int src = ((i >> 7) <= (j >> 7)) ? (i * DD + j) : (j * DD + i);
            float s = 0.f;
#pragma unroll
            for (int z = 0; z < NSPLIT; z++)
                s += g_covpart[(size_t)z * DD * DD + src];
            g_sig[idx] = s * (1.0f / (float)NROWS) - g_mean[i] * g_mean[j];
        }
        gridbar();
    }

    tgemm<2, 1>(g_T1, g_sig, W, nullptr, 1.0f, 0, 0, rS, cS, As, Bs, bsAddr);
    gridbar();
    tgemm<2, 1>(g_cov, W, g_T1, nullptr, 1.0f, 1, 1, rS, cS, As, Bs, bsAddr);
    gridbar();
    if (tile == 0) {
        float s = g_cov[(size_t)(2 * tid) * (DD + 1)]
                + g_cov[(size_t)(2 * tid + 1) * (DD + 1)];
        red[tid] = s;
        __syncthreads();
        for (int k = 128; k > 0; k >>= 1) {
            if (tid < k) red[tid] += red[tid + k];
            __syncthreads();
        }
        if (tid == 0) {
            float tr = red[0];
            g_scal[0] = 1.0f / tr;
            g_scal[1] = 1.0f / sqrtf(tr);
        }
    }
    gridbar();
    {
        const float s0 = g_scal[0];
#pragma unroll
        for (int q = 0; q < 4; q++) {
            int idx = tile * 1024 + q * 256 + tid;
            int i = idx >> 9, j = idx & (DD - 1);
            g_P0[idx] = ((i == j) ? 1.5f : 0.0f) - 0.5f * g_cov[idx] * s0;
        }
    }
    gridbar();

    float* P = g_P0;
    float* Pn = g_P1;
    for (int it = 1; it < 10; it++) {
        if (tile < 128)
            tgemm<4, 1>(g_A1, P, P, nullptr, 1.0f, 0, 0, rD, cD, As, Bs, bsAddr);
        else
            tgemm<4, 1>(g_A2, P, g_cov, nullptr, g_scal[0], 0, 0, rD, cD, As, Bs, bsAddr);
        gridbar();
        tgemm<2, 1>(Pn, g_A1, g_A2, P, 1.0f, 2, 0, rS, cS, As, Bs, bsAddr);
        gridbar();
        float* t = P; P = Pn; Pn = t;
    }

    if (tile < 128)
        tgemm<4, 1>(g_A2, P, g_cov, P, g_scal[0], 3, 0, rD, cD, As, Bs, bsAddr);
    else
        tgemm<4, 1>(g_M, W, P, nullptr, g_scal[1], 0, 0, rD, cD, As, Bs, bsAddr);
    gridbar();
    if (tile < 128) {
        tgemm<4, 1>(g_sig, P, g_A2, nullptr, 1.0f, 0, 0, rD, cD, As, Bs, bsAddr);
    } else if (isL0) {
#pragma unroll
        for (int q = 0; q < 8; q++) {
            int idx = (tile - 128) * 2048 + q * 256 + tid;
            MeffOut[idx] = g_M[idx];
        }
    } else {
        tgemm<4, 1>(MeffOut, MeffPrev, g_M, nullptr, 1.0f, 0, 0, rD, cD, As, Bs, bsAddr);
    }
    gridbar();
    // f3: 256 CTAs each transpose-split one 32x32 block; warps 0-1 also do mc
    {
        const int i32 = tile >> 4, j32 = tile & 15;
        int r = tid >> 3, c = (tid & 7) * 4;
        float4 v = *(const float4*)(MeffOut + (size_t)(i32 * 32 + r) * DD
                                    + j32 * 32 + c);
        tsub[r][c] = v.x; tsub[r][c + 1] = v.y;
        tsub[r][c + 2] = v.z; tsub[r][c + 3] = v.w;
        __syncthreads();
        int cc = tid >> 3, rr = (tid & 7) * 4;
        bf16 h[4], l[4];
#pragma unroll
        for (int i = 0; i < 4; i++) split2(tsub[rr + i][cc], h[i], l[i]);
        size_t off = (size_t)(j32 * 32 + cc) * DD + i32 * 32 + rr;
        *(uint2*)(w0 + off) = make_uint2(pack2(h[0], h[1]), pack2(h[2], h[3]));
        *(uint2*)(w1 + off) = make_uint2(pack2(l[0], l[1]), pack2(l[2], l[3]));

        const int wid = tid >> 5;
        if (wid < 2) {
            const int col = tile * 2 + wid;
            float s = 0.f;
            for (int k = lane; k < DD; k += 32)
                s += g_mean[k] * MeffOut[(size_t)k * DD + col];
#pragma unroll
            for (int o = 16; o > 0; o >>= 1)
                s += __shfl_down_sync(0xffffffffu, s, o);
            if (lane == 0) mc[col] = s;
        }
    }
}

// ---------------------------------------------------------------------------
// orchestration (round-14/15 structure; chain L0 = our 4th launch for ncu)
// ---------------------------------------------------------------------------
static cudaStream_t s2, sO1, sO2;
static cudaEvent_t evRoot, evGram, evSplit, evM[3], evO1, evO2;
static bool g_inited = false;

extern "C" void kernel_launch(void* const* d_in, const int* in_sizes, int n_in,
                              void* d_out, int out_size) {
    (void)in_sizes; (void)n_in; (void)out_size;
    const float* x = (const float*)d_in[0];
    const float* W[3] = {(const float*)d_in[1], (const float*)d_in[2],
                         (const float*)d_in[3]};
    float* out = (float*)d_out;

    float *pcovpart, *pmc, *pMA, *pMB;
    bf16 *psA0, *psA1, *pt0, *pt1, *pw0, *pw1;
    cudaGetSymbolAddress((void**)&pcovpart, g_covpart);
    cudaGetSymbolAddress((void**)&pmc, g_mcv);
    cudaGetSymbolAddress((void**)&pMA, g_MeffA);
    cudaGetSymbolAddress((void**)&pMB, g_MeffB);
    cudaGetSymbolAddress((void**)&psA0, g_sA0);
    cudaGetSymbolAddress((void**)&psA1, g_sA1);
    cudaGetSymbolAddress((void**)&pt0, g_t0);
    cudaGetSymbolAddress((void**)&pt1, g_t1);
    cudaGetSymbolAddress((void**)&pw0, g_w0);
    cudaGetSymbolAddress((void**)&pw1, g_w1);

    if (!g_inited) {
        g_inited = true;
        cudaFuncSetAttribute(mma_gemm<2>, cudaFuncAttributeMaxDynamicSharedMemorySize, SMEMSZ);
        cudaFuncSetAttribute(mma_gemm<3>, cudaFuncAttributeMaxDynamicSharedMemorySize, SMEMSZ);
        cudaStreamCreateWithFlags(&s2, cudaStreamNonBlocking);
        cudaStreamCreateWithFlags(&sO1, cudaStreamNonBlocking);
        cudaStreamCreateWithFlags(&sO2, cudaStreamNonBlocking);
        cudaEventCreateWithFlags(&evRoot, cudaEventDisableTiming);
        cudaEventCreateWithFlags(&evGram, cudaEventDisableTiming);
        cudaEventCreateWithFlags(&evSplit, cudaEventDisableTiming);
        for (int i = 0; i < 3; i++)
            cudaEventCreateWithFlags(&evM[i], cudaEventDisableTiming);
        cudaEventCreateWithFlags(&evO1, cudaEventDisableTiming);
        cudaEventCreateWithFlags(&evO2, cudaEventDisableTiming);
    }

    const int N4BIG = NROWS * DD / 4;
    const dim3 gact(4, NROWS / 128);
    const dim3 gcov(10, 1, NSPLIT);

    split_trans2_kernel<<<dim3(NROWS / 32, 16), 256>>>(x, pt0, pt1, NROWS);     // #1
    cudaEventRecord(evRoot, 0);
    cudaStreamWaitEvent(s2, evRoot, 0);

    colsum_kernel<<<256, 512, 0, s2>>>(x);                                      // #2
    mma_gemm<2><<<gcov, 256, SMEMSZ>>>(pt0, pt1, pt0, pt1, pcovpart, nullptr);  // #3
    cudaEventRecord(evGram, 0);

    cudaStreamWaitEvent(s2, evGram, 0);
    persist_chain<<<PCTAS, 256, 0, s2>>>(W[0], pw0, pw1, pmc,
                                         nullptr, pMA, 1);                      // #4 (ncu)
    cudaEventRecord(evM[0], s2);

    split_rows2_kernel<<<N4BIG / 256, 256>>>(x, psA0, psA1, N4BIG);             // #5
    cudaEventRecord(evSplit, 0);

    persist_chain<<<PCTAS, 256, 0, s2>>>(W[1], pw0 + (size_t)DD * DD,
                                         pw1 + (size_t)DD * DD, pmc + DD,
                                         pMA, pMB, 0);                          // #6
    cudaEventRecord(evM[1], s2);
    persist_chain<<<PCTAS, 256, 0, s2>>>(W[2], pw0 + (size_t)2 * DD * DD,
                                         pw1 + (size_t)2 * DD * DD, pmc + 2 * DD,
                                         pMB, pMA, 0);                          // #7
    cudaEventRecord(evM[2], s2);

    cudaStreamWaitEvent(0, evM[0], 0);
    mma_gemm<3><<<gact, 256, SMEMSZ>>>(psA0, psA1, pw0, pw1, out, pmc);         // #8

    cudaStreamWaitEvent(sO1, evSplit, 0);
    cudaStreamWaitEvent(sO1, evM[1], 0);
    mma_gemm<3><<<gact, 256, SMEMSZ, sO1>>>(psA0, psA1,
                                            pw0 + (size_t)DD * DD,
                                            pw1 + (size_t)DD * DD,
                                            out + (size_t)NROWS * DD, pmc + DD); // #9
    cudaEventRecord(evO1, sO1);

    cudaStreamWaitEvent(sO2, evSplit, 0);
    cudaStreamWaitEvent(sO2, evM[2], 0);
    mma_gemm<3><<<gact, 256, SMEMSZ, sO2>>>(psA0, psA1,
                                            pw0 + (size_t)2 * DD * DD,
                                            pw1 + (size_t)2 * DD * DD,
                                            out + (size_t)2 * NROWS * DD,
                                            pmc + 2 * DD);                       // #10
    cudaEventRecord(evO2, sO2);

    cudaStreamWaitEvent(0, evO1, 0);
    cudaStreamWaitEvent(0, evO2, 0);
}